// round 13
// baseline (speedup 1.0000x reference)
#include <cuda_runtime.h>
#include <cuda_fp16.h>
#include <cstdint>

#define N_NODES   131072
#define NODES_PER 2048
#define B_AUD     64
#define IN_F      512
#define HID_F     256
#define OUT_F     128
#define NHEAD     2
#define NCLS      7
#define NEG_SLOPE 0.2f

// ---------------- scratch (static device allocations; no cudaMalloc) ----------------
__device__ __half g_h1raw[(size_t)N_NODES * NHEAD * HID_F]; // 128 MB (fp16)
__device__ __half g_h2raw[(size_t)N_NODES * NHEAD * OUT_F]; //  64 MB (fp16)
__device__ float  g_emb  [(size_t)N_NODES * OUT_F];         //  64 MB
__device__ __half g_xh  [(size_t)N_NODES * IN_F];
__device__ __half g_h1h [(size_t)N_NODES * HID_F];
__device__ __half g_w1h [512 * 512];
__device__ __half g_w2h [256 * 256];
__device__ float g_als1[N_NODES * NHEAD];
__device__ float g_ald1[N_NODES * NHEAD];
__device__ float g_als2[N_NODES * NHEAD];
__device__ float g_ald2[N_NODES * NHEAD];
__device__ float g_logit[N_NODES];
__device__ float g_aw   [B_AUD * NODES_PER];
__device__ float g_att  [B_AUD * OUT_F];

__device__ __forceinline__ float lrelu(float v) { return v > 0.f ? v : NEG_SLOPE * v; }

// ---------------- PTX helpers (portable: sm_80-class, compiles at compute_103) ----------------
__device__ __forceinline__ uint32_t smem_u32(const void* p) {
    uint32_t a;
    asm("{ .reg .u64 t; cvta.to.shared.u64 t, %1; cvt.u32.u64 %0, t; }" : "=r"(a) : "l"(p));
    return a;
}
__device__ __forceinline__ uint32_t swz(uint32_t b) { return b ^ ((b >> 3) & 0x70); }
__device__ __forceinline__ void cp16(uint32_t dst, const void* src) {
    asm volatile("cp.async.cg.shared.global [%0], [%1], 16;" :: "r"(dst), "l"(src));
}
__device__ __forceinline__ void ldm_x4(uint32_t* r, uint32_t addr) {
    asm volatile("ldmatrix.sync.aligned.m8n8.x4.shared.b16 {%0,%1,%2,%3}, [%4];"
                 : "=r"(r[0]), "=r"(r[1]), "=r"(r[2]), "=r"(r[3]) : "r"(addr));
}
__device__ __forceinline__ void mma_f16(float* c, const uint32_t* a, uint32_t b0, uint32_t b1) {
    asm volatile(
        "mma.sync.aligned.m16n8k16.row.col.f32.f16.f16.f32 "
        "{%0,%1,%2,%3}, {%4,%5,%6,%7}, {%8,%9}, {%0,%1,%2,%3};"
        : "+f"(c[0]), "+f"(c[1]), "+f"(c[2]), "+f"(c[3])
        : "r"(a[0]), "r"(a[1]), "r"(a[2]), "r"(a[3]), "r"(b0), "r"(b1));
}

// ---------------- fp32 -> fp16 convert ----------------
__global__ __launch_bounds__(256)
void cvt_f16(const float* __restrict__ a, __half* __restrict__ o, int n4) {
    int i = blockIdx.x * 256 + threadIdx.x;
    if (i >= n4) return;
    float4 v = ((const float4*)a)[i];
    __half2 p0; p0.x = __float2half(v.x); p0.y = __float2half(v.y);
    __half2 p1; p1.x = __float2half(v.z); p1.y = __float2half(v.w);
    ((__half2*)o)[2 * i]     = p0;
    ((__half2*)o)[2 * i + 1] = p1;
}

// ---------------- fp16 warp-MMA GEMM: C(fp16) = A * B^T, fused al-epilogue ----------------
// CTA 128x256, BK=64; 3-stage cp.async, one __syncthreads per iter (early-load);
// 8 warps in 2m x 4n, warp tile 64x64: 8 ldmatrix / 32 MMA per kk per warp.
#define STG_A     0
#define STG_B     16384
#define STG_BYTES 49152
#define GEMM_SMEM (3 * STG_BYTES)

template <int K, int MT>
__global__ __launch_bounds__(256, 1)
void gemm_mma(const __half* __restrict__ A, const __half* __restrict__ B,
              __half* __restrict__ C,
              const float* __restrict__ ws_flat, const float* __restrict__ wd_flat,
              float* __restrict__ alsP, float* __restrict__ aldP) {
    extern __shared__ __align__(1024) char smem[];
    uint32_t sb = smem_u32(smem);
    const int tid = threadIdx.x, wid = tid >> 5, lane = tid & 31;
    const int row0 = blockIdx.y * 128, col0 = blockIdx.x * 256;
    const int warp_m = wid >> 2;   // 0..1 -> 64 rows each
    const int warp_n = wid & 3;    // 0..3 -> 64 cols each
    constexpr int NIT = K / 64;

    auto load = [&](int it) {
        uint32_t st = sb + (it % 3) * STG_BYTES;
#pragma unroll
        for (int i = 0; i < 4; i++) {       // A: 128 x 64 fp16 = 1024 x 16B
            int idx = tid + i * 256;
            int r = idx >> 3, c16 = idx & 7;
            uint32_t so = swz(r * 128 + c16 * 16);
            cp16(st + STG_A + so, A + (size_t)(row0 + r) * K + it * 64 + c16 * 8);
        }
#pragma unroll
        for (int i = 0; i < 8; i++) {       // B: 256 x 64 fp16 = 2048 x 16B
            int idx = tid + i * 256;
            int r = idx >> 3, c16 = idx & 7;
            uint32_t so = swz(r * 128 + c16 * 16);
            cp16(st + STG_B + so, B + (size_t)(col0 + r) * K + it * 64 + c16 * 8);
        }
        asm volatile("cp.async.commit_group;" ::: "memory");
    };

    float acc[4][8][4] = {};   // [m16 block][n8 block][frag]

    load(0);
    if (NIT > 1) load(1);

    const int lrow = lane & 15, lhi = lane >> 4;

#pragma unroll 1
    for (int it = 0; it < NIT; it++) {
        if (NIT > 1) asm volatile("cp.async.wait_group 1;" ::: "memory");
        else         asm volatile("cp.async.wait_group 0;" ::: "memory");
        __syncthreads();
        if (it + 2 < NIT) load(it + 2);   // writes oldest stage; readers retired by barrier above

        uint32_t st = sb + (it % 3) * STG_BYTES;
#pragma unroll
        for (int kk = 0; kk < 4; kk++) {
            uint32_t a[4][4];
#pragma unroll
            for (int mt = 0; mt < 4; mt++)
                ldm_x4(a[mt], st + STG_A + swz((warp_m * 64 + mt * 16 + lrow) * 128 + (kk * 2 + lhi) * 16));
#pragma unroll
            for (int bf = 0; bf < 4; bf++) {
                uint32_t b[4];
                ldm_x4(b, st + STG_B + swz((warp_n * 64 + bf * 16 + lrow) * 128 + (kk * 2 + lhi) * 16));
#pragma unroll
                for (int mt = 0; mt < 4; mt++) {
                    mma_f16(acc[mt][bf * 2 + 0], a[mt], b[0], b[2]);
                    mma_f16(acc[mt][bf * 2 + 1], a[mt], b[1], b[3]);
                }
            }
        }
    }
    __syncthreads();   // smem about to be reused as reduction buffer

    // ---- epilogue 1: store C tile as fp16 ----
#pragma unroll
    for (int mt = 0; mt < 4; mt++) {
        int row = row0 + warp_m * 64 + mt * 16 + (lane >> 2);
#pragma unroll
        for (int nb = 0; nb < 8; nb++) {
            int col = col0 + warp_n * 64 + nb * 8 + (lane & 3) * 2;
            __half2 v0; v0.x = __float2half(acc[mt][nb][0]); v0.y = __float2half(acc[mt][nb][1]);
            __half2 v1; v1.x = __float2half(acc[mt][nb][2]); v1.y = __float2half(acc[mt][nb][3]);
            *(__half2*)&C[(size_t)row * MT + col]       = v0;
            *(__half2*)&C[(size_t)(row + 8) * MT + col] = v1;
        }
    }

    // ---- epilogue 2: attention logits (single-slot: CTA spans whole heads) ----
    constexpr int C_HEAD      = MT / NHEAD;        // 256 (MT=512) or 128 (MT=256)
    constexpr int WN_PER_HEAD = C_HEAD / 64;       // 4 or 2
    constexpr int HPC         = 4 / WN_PER_HEAD;   // 1 or 2 heads per CTA
    float* bufss = (float*)smem;                   // [4 warp_n][128 rows]
    float* bufsd = bufss + 512;

#pragma unroll
    for (int mt = 0; mt < 4; mt++) {
        float ss0 = 0.f, ss1 = 0.f, sd0 = 0.f, sd1 = 0.f;
#pragma unroll
        for (int nb = 0; nb < 8; nb++) {
            int c = col0 + warp_n * 64 + nb * 8 + (lane & 3) * 2;
            float w0s = ws_flat[c], w1s = ws_flat[c + 1];
            float w0d = wd_flat[c], w1d = wd_flat[c + 1];
            ss0 = fmaf(acc[mt][nb][0], w0s, fmaf(acc[mt][nb][1], w1s, ss0));
            ss1 = fmaf(acc[mt][nb][2], w0s, fmaf(acc[mt][nb][3], w1s, ss1));
            sd0 = fmaf(acc[mt][nb][0], w0d, fmaf(acc[mt][nb][1], w1d, sd0));
            sd1 = fmaf(acc[mt][nb][2], w0d, fmaf(acc[mt][nb][3], w1d, sd1));
        }
#pragma unroll
        for (int off = 1; off <= 2; off <<= 1) {
            ss0 += __shfl_xor_sync(0xffffffffu, ss0, off);
            ss1 += __shfl_xor_sync(0xffffffffu, ss1, off);
            sd0 += __shfl_xor_sync(0xffffffffu, sd0, off);
            sd1 += __shfl_xor_sync(0xffffffffu, sd1, off);
        }
        if ((lane & 3) == 0) {
            int r0 = warp_m * 64 + mt * 16 + (lane >> 2);
            bufss[warp_n * 128 + r0]     = ss0;
            bufss[warp_n * 128 + r0 + 8] = ss1;
            bufsd[warp_n * 128 + r0]     = sd0;
            bufsd[warp_n * 128 + r0 + 8] = sd1;
        }
    }
    __syncthreads();
    if (tid < 128) {
        size_t node = (size_t)(row0 + tid);
#pragma unroll
        for (int hc = 0; hc < HPC; hc++) {
            float ss = 0.f, sd = 0.f;
#pragma unroll
            for (int w = 0; w < WN_PER_HEAD; w++) {
                ss += bufss[(hc * WN_PER_HEAD + w) * 128 + tid];
                sd += bufsd[(hc * WN_PER_HEAD + w) * 128 + tid];
            }
            int head = col0 / C_HEAD + hc;
            alsP[node * NHEAD + head] = ss;
            aldP[node * NHEAD + head] = sd;
        }
    }
}

// ---------------- layer-1 GAT combine, vectorized: 4 nodes per block, fp16 in/out ----------------
__global__ __launch_bounds__(256)
void gat_combine_l1(const __half* __restrict__ hraw, const float* __restrict__ alsP,
                    const float* __restrict__ aldP, const float* __restrict__ bias,
                    __half* __restrict__ out_hi) {
    int tid = threadIdx.x;
    int d   = blockIdx.x * 4 + (tid >> 6);
    int c4  = (tid & 63) * 4;
    bool has_prev = (d % NODES_PER) != 0;

    float4 r = *(const float4*)&bias[c4];
    float acc0 = r.x, acc1 = r.y, acc2 = r.z, acc3 = r.w;
    float o0 = 0.f, o1 = 0.f, o2 = 0.f, o3 = 0.f;
#pragma unroll
    for (int hh = 0; hh < NHEAD; hh++) {
        size_t ai = (size_t)d * NHEAD + hh;
        float als = alsP[ai];
        float ald = aldP[ai];
        float es  = lrelu(als + ald);
        const __half2* hsp = (const __half2*)&hraw[(size_t)d * NHEAD * HID_F + hh * HID_F + c4];
        float2 hs01 = __half22float2(hsp[0]);
        float2 hs23 = __half22float2(hsp[1]);
        if (has_prev) {
            float alsp = alsP[(size_t)(d - 1) * NHEAD + hh];
            float ep = lrelu(alsp + ald);
            float m  = fmaxf(es, ep);
            float xs = __expf(es - m), xp = __expf(ep - m);
            float inv = 0.5f / (xs + xp);
            xs *= inv; xp *= inv;
            const __half2* hpp = (const __half2*)&hraw[(size_t)(d - 1) * NHEAD * HID_F + hh * HID_F + c4];
            float2 hp01 = __half22float2(hpp[0]);
            float2 hp23 = __half22float2(hpp[1]);
            o0 += xs * hs01.x + xp * hp01.x;
            o1 += xs * hs01.y + xp * hp01.y;
            o2 += xs * hs23.x + xp * hp23.x;
            o3 += xs * hs23.y + xp * hp23.y;
        } else {
            o0 += 0.5f * hs01.x; o1 += 0.5f * hs01.y;
            o2 += 0.5f * hs23.x; o3 += 0.5f * hs23.y;
        }
    }
    acc0 = fmaxf(acc0 + o0, 0.f);
    acc1 = fmaxf(acc1 + o1, 0.f);
    acc2 = fmaxf(acc2 + o2, 0.f);
    acc3 = fmaxf(acc3 + o3, 0.f);

    __half2 ph0; ph0.x = __float2half(acc0); ph0.y = __float2half(acc1);
    __half2 ph1; ph1.x = __float2half(acc2); ph1.y = __float2half(acc3);
    size_t gid2 = ((size_t)d * HID_F + c4) >> 1;
    ((__half2*)out_hi)[gid2]     = ph0;
    ((__half2*)out_hi)[gid2 + 1] = ph1;
}

// ---------------- layer-2 combine + node heads, warp per node (fp16 h2raw) ----------------
__global__ __launch_bounds__(256)
void gat_l2_fused(const __half* __restrict__ h2raw, const float* __restrict__ alsP,
                  const float* __restrict__ aldP, const float* __restrict__ b2,
                  const float* __restrict__ Wn, const float* __restrict__ bn,
                  const float* __restrict__ Wt, const float* __restrict__ bt,
                  float* __restrict__ emb, float* __restrict__ node_pred,
                  float* __restrict__ logit) {
    int d    = (blockIdx.x * blockDim.x + threadIdx.x) >> 5;
    int lane = threadIdx.x & 31;
    if (d >= N_NODES) return;
    bool has_prev = (d % NODES_PER) != 0;

    float e[4] = {0.f, 0.f, 0.f, 0.f};
#pragma unroll
    for (int hh = 0; hh < NHEAD; hh++) {
        size_t ai = (size_t)d * NHEAD + hh;
        float als = alsP[ai];
        float ald = aldP[ai];
        float es  = lrelu(als + ald);
        const __half2* hsp = (const __half2*)&h2raw[(size_t)d * NHEAD * OUT_F + hh * OUT_F + lane * 4];
        float2 hs01 = __half22float2(hsp[0]);
        float2 hs23 = __half22float2(hsp[1]);
        if (has_prev) {
            float alsp = alsP[(size_t)(d - 1) * NHEAD + hh];
            float ep = lrelu(alsp + ald);
            float m  = fmaxf(es, ep);
            float xs = __expf(es - m), xp = __expf(ep - m);
            float inv = 1.f / (xs + xp);
            const __half2* hpp = (const __half2*)&h2raw[(size_t)(d - 1) * NHEAD * OUT_F + hh * OUT_F + lane * 4];
            float2 hp01 = __half22float2(hpp[0]);
            float2 hp23 = __half22float2(hpp[1]);
            e[0] += (xs * hs01.x + xp * hp01.x) * inv;
            e[1] += (xs * hs01.y + xp * hp01.y) * inv;
            e[2] += (xs * hs23.x + xp * hp23.x) * inv;
            e[3] += (xs * hs23.y + xp * hp23.y) * inv;
        } else {
            e[0] += hs01.x; e[1] += hs01.y; e[2] += hs23.x; e[3] += hs23.y;
        }
    }
    float4 bb = *(const float4*)&b2[lane * 4];
    e[0] = e[0] * 0.5f + bb.x;
    e[1] = e[1] * 0.5f + bb.y;
    e[2] = e[2] * 0.5f + bb.z;
    e[3] = e[3] * 0.5f + bb.w;
    float4 ev; ev.x = e[0]; ev.y = e[1]; ev.z = e[2]; ev.w = e[3];
    *(float4*)&emb[(size_t)d * OUT_F + lane * 4] = ev;

    float vals[8];
#pragma unroll
    for (int o = 0; o < 8; o++) {
        const float* w = (o < NCLS) ? &Wn[o * OUT_F] : Wt;
        float4 w4 = *(const float4*)&w[lane * 4];
        float s = e[0] * w4.x + e[1] * w4.y + e[2] * w4.z + e[3] * w4.w;
#pragma unroll
        for (int sh = 16; sh; sh >>= 1) s += __shfl_xor_sync(0xffffffffu, s, sh);
        vals[o] = s;
    }
    if (lane == 0) {
        float z[NCLS], m = -1e30f;
#pragma unroll
        for (int i = 0; i < NCLS; i++) { z[i] = vals[i] + bn[i]; m = fmaxf(m, z[i]); }
        float ssum = 0.f;
#pragma unroll
        for (int i = 0; i < NCLS; i++) { z[i] = __expf(z[i] - m); ssum += z[i]; }
        float inv = 1.f / ssum;
#pragma unroll
        for (int i = 0; i < NCLS; i++) node_pred[(size_t)d * NCLS + i] = z[i] * inv;
        logit[d] = vals[7] + bt[0];
    }
}

// ---------------- audio pooling, stage 1: per-audio softmax weights ----------------
__global__ __launch_bounds__(256)
void audio_softmax(const float* __restrict__ logit, float* __restrict__ aw) {
    __shared__ float red[256];
    int b = blockIdx.x, t = threadIdx.x;
    const float* lg = logit + b * NODES_PER;

    float m = -1e30f;
    for (int i = t; i < NODES_PER; i += 256) m = fmaxf(m, lg[i]);
    red[t] = m; __syncthreads();
    for (int s = 128; s; s >>= 1) { if (t < s) red[t] = fmaxf(red[t], red[t + s]); __syncthreads(); }
    m = red[0]; __syncthreads();

    float e0 = __expf(lg[t] - m);
    float e1 = __expf(lg[t + 256] - m);
    float e2 = __expf(lg[t + 512] - m);
    float e3 = __expf(lg[t + 768] - m);
    float e4 = __expf(lg[t + 1024] - m);
    float e5 = __expf(lg[t + 1280] - m);
    float e6 = __expf(lg[t + 1536] - m);
    float e7 = __expf(lg[t + 1792] - m);
    red[t] = ((e0 + e1) + (e2 + e3)) + ((e4 + e5) + (e6 + e7));
    __syncthreads();
    for (int s = 128; s; s >>= 1) { if (t < s) red[t] += red[t + s]; __syncthreads(); }
    float inv = 1.f / red[0];
    float* dst = aw + b * NODES_PER;
    dst[t]        = e0 * inv;
    dst[t + 256]  = e1 * inv;
    dst[t + 512]  = e2 * inv;
    dst[t + 768]  = e3 * inv;
    dst[t + 1024] = e4 * inv;
    dst[t + 1280] = e5 * inv;
    dst[t + 1536] = e6 * inv;
    dst[t + 1792] = e7 * inv;
}

// ---------------- audio pooling, stage 2: weighted sum (chunked, coalesced) ----------------
__global__ __launch_bounds__(256)
void audio_wsum(const float* __restrict__ emb, const float* __restrict__ aw,
                float* __restrict__ att) {
    __shared__ float red[8][33];
    int chunk = blockIdx.x, b = blockIdx.y;
    int w = threadIdx.x >> 5, lane = threadIdx.x & 31;
    int ch = chunk * 32 + lane;
    const float* eb = emb + (size_t)b * NODES_PER * OUT_F + ch;
    const float* wb = aw + b * NODES_PER;

    float a0 = 0.f, a1 = 0.f;
    int i0 = w * 256;
#pragma unroll 4
    for (int i = 0; i < 256; i += 2) {
        a0 = fmaf(wb[i0 + i],     eb[(size_t)(i0 + i) * OUT_F],     a0);
        a1 = fmaf(wb[i0 + i + 1], eb[(size_t)(i0 + i + 1) * OUT_F], a1);
    }
    red[w][lane] = a0 + a1;
    __syncthreads();
    if (w == 0) {
        float s = red[0][lane];
#pragma unroll
        for (int j = 1; j < 8; j++) s += red[j][lane];
        att[b * OUT_F + ch] = s;
    }
}

// ---------------- audio pooling, stage 3: Wa head ----------------
__global__ __launch_bounds__(128)
void audio_head(const float* __restrict__ att, const float* __restrict__ Wa,
                const float* __restrict__ ba, float* __restrict__ audio_pred) {
    __shared__ float red[128];
    int b = blockIdx.x, t = threadIdx.x;
    float a = att[b * OUT_F + t];
#pragma unroll
    for (int o = 0; o < 2; o++) {
        red[t] = a * Wa[o * OUT_F + t]; __syncthreads();
        for (int s = 64; s; s >>= 1) { if (t < s) red[t] += red[t + s]; __syncthreads(); }
        if (t == 0) audio_pred[b * 2 + o] = red[0] + ba[o];
        __syncthreads();
    }
}

// ---------------- launch ----------------
extern "C" void kernel_launch(void* const* d_in, const int* in_sizes, int n_in,
                              void* d_out, int out_size) {
    int wi = n_in - 14;
    const float* x   = (const float*)d_in[0];
    const float* W1  = (const float*)d_in[wi + 0];
    const float* as1 = (const float*)d_in[wi + 1];
    const float* ad1 = (const float*)d_in[wi + 2];
    const float* b1  = (const float*)d_in[wi + 3];
    const float* W2  = (const float*)d_in[wi + 4];
    const float* as2 = (const float*)d_in[wi + 5];
    const float* ad2 = (const float*)d_in[wi + 6];
    const float* b2  = (const float*)d_in[wi + 7];
    const float* Wt  = (const float*)d_in[wi + 8];
    const float* bt  = (const float*)d_in[wi + 9];
    const float* Wa  = (const float*)d_in[wi + 10];
    const float* ba  = (const float*)d_in[wi + 11];
    const float* Wn  = (const float*)d_in[wi + 12];
    const float* bn  = (const float*)d_in[wi + 13];

    float *emb, *als1, *ald1, *als2, *ald2, *logit, *aw, *att;
    __half *h1raw, *h2raw, *xh, *h1h, *w1h, *w2h;
    cudaGetSymbolAddress((void**)&h1raw, g_h1raw);
    cudaGetSymbolAddress((void**)&h2raw, g_h2raw);
    cudaGetSymbolAddress((void**)&emb,   g_emb);
    cudaGetSymbolAddress((void**)&xh,    g_xh);
    cudaGetSymbolAddress((void**)&h1h,   g_h1h);
    cudaGetSymbolAddress((void**)&w1h,   g_w1h);
    cudaGetSymbolAddress((void**)&w2h,   g_w2h);
    cudaGetSymbolAddress((void**)&als1,  g_als1);
    cudaGetSymbolAddress((void**)&ald1,  g_ald1);
    cudaGetSymbolAddress((void**)&als2,  g_als2);
    cudaGetSymbolAddress((void**)&ald2,  g_ald2);
    cudaGetSymbolAddress((void**)&logit, g_logit);
    cudaGetSymbolAddress((void**)&aw,    g_aw);
    cudaGetSymbolAddress((void**)&att,   g_att);

    float* node_pred  = (float*)d_out;
    float* audio_pred = node_pred + (size_t)N_NODES * NCLS;

    cudaFuncSetAttribute((const void*)gemm_mma<512, 512>, cudaFuncAttributeMaxDynamicSharedMemorySize, GEMM_SMEM);
    cudaFuncSetAttribute((const void*)gemm_mma<256, 256>, cudaFuncAttributeMaxDynamicSharedMemorySize, GEMM_SMEM);

    // conversions (all single fp16)
    cvt_f16<<<(N_NODES * IN_F / 4 + 255) / 256, 256>>>(x, xh, N_NODES * IN_F / 4);
    cvt_f16<<<(512 * 512 / 4 + 255) / 256, 256>>>(W1, w1h, 512 * 512 / 4);
    cvt_f16<<<(256 * 256 / 4 + 255) / 256, 256>>>(W2, w2h, 256 * 256 / 4);

    // layer 1: h1raw(fp16) = x @ W1^T [N,512] + fused al1
    gemm_mma<512, 512><<<dim3(2, N_NODES / 128), 256, GEMM_SMEM>>>(
        xh, w1h, h1raw, as1, ad1, als1, ald1);
    gat_combine_l1<<<N_NODES / 4, 256>>>(h1raw, als1, ald1, b1, h1h);

    // layer 2: h2raw(fp16) = h1 @ W2^T [N,256] + fused al2
    gemm_mma<256, 256><<<dim3(1, N_NODES / 128), 256, GEMM_SMEM>>>(
        h1h, w2h, h2raw, as2, ad2, als2, ald2);
    gat_l2_fused<<<N_NODES / 8, 256>>>(h2raw, als2, ald2, b2, Wn, bn, Wt, bt,
                                       emb, node_pred, logit);

    // audio head (3-stage, parallel)
    audio_softmax<<<B_AUD, 256>>>(logit, aw);
    audio_wsum<<<dim3(4, B_AUD), 256>>>(emb, aw, att);
    audio_head<<<B_AUD, 128>>>(att, Wa, ba, audio_pred);
}

// round 14
// speedup vs baseline: 1.1136x; 1.1136x over previous
#include <cuda_runtime.h>
#include <cuda_fp16.h>
#include <cstdint>

#define N_NODES   131072
#define NODES_PER 2048
#define B_AUD     64
#define IN_F      512
#define HID_F     256
#define OUT_F     128
#define NHEAD     2
#define NCLS      7
#define NEG_SLOPE 0.2f
#define PART_STRIDE ((size_t)N_NODES * NHEAD)

// ---------------- scratch (static device allocations; no cudaMalloc) ----------------
__device__ __half g_h1raw[(size_t)N_NODES * NHEAD * HID_F]; // 128 MB (fp16)
__device__ __half g_h2raw[(size_t)N_NODES * NHEAD * OUT_F]; //  64 MB (fp16)
__device__ float  g_emb  [(size_t)N_NODES * OUT_F];         //  64 MB
__device__ __half g_xh  [(size_t)N_NODES * IN_F];
__device__ __half g_h1h [(size_t)N_NODES * HID_F];
__device__ __half g_w1h [512 * 512];
__device__ __half g_w2h [256 * 256];
__device__ float g_als1p[2 * PART_STRIDE];
__device__ float g_ald1p[2 * PART_STRIDE];
__device__ float g_als2p[2 * PART_STRIDE];
__device__ float g_ald2p[2 * PART_STRIDE];
__device__ float g_logit[N_NODES];
__device__ float g_aw   [B_AUD * NODES_PER];
__device__ float g_att  [B_AUD * OUT_F];

__device__ __forceinline__ float lrelu(float v) { return v > 0.f ? v : NEG_SLOPE * v; }

// ---------------- PTX helpers (portable: sm_80-class, compiles at compute_103) ----------------
__device__ __forceinline__ uint32_t smem_u32(const void* p) {
    uint32_t a;
    asm("{ .reg .u64 t; cvta.to.shared.u64 t, %1; cvt.u32.u64 %0, t; }" : "=r"(a) : "l"(p));
    return a;
}
__device__ __forceinline__ uint32_t swz(uint32_t b) { return b ^ ((b >> 3) & 0x70); }
__device__ __forceinline__ void cp16(uint32_t dst, const void* src) {
    asm volatile("cp.async.cg.shared.global [%0], [%1], 16;" :: "r"(dst), "l"(src));
}
__device__ __forceinline__ void ldm_x4(uint32_t* r, uint32_t addr) {
    asm volatile("ldmatrix.sync.aligned.m8n8.x4.shared.b16 {%0,%1,%2,%3}, [%4];"
                 : "=r"(r[0]), "=r"(r[1]), "=r"(r[2]), "=r"(r[3]) : "r"(addr));
}
__device__ __forceinline__ void mma_f16(float* c, const uint32_t* a, uint32_t b0, uint32_t b1) {
    asm volatile(
        "mma.sync.aligned.m16n8k16.row.col.f32.f16.f16.f32 "
        "{%0,%1,%2,%3}, {%4,%5,%6,%7}, {%8,%9}, {%0,%1,%2,%3};"
        : "+f"(c[0]), "+f"(c[1]), "+f"(c[2]), "+f"(c[3])
        : "r"(a[0]), "r"(a[1]), "r"(a[2]), "r"(a[3]), "r"(b0), "r"(b1));
}

// ---------------- merged fp32 -> fp16 convert: x, W1, W2 in one launch ----------------
#define N4_X  (N_NODES * IN_F / 4)
#define N4_W1 (512 * 512 / 4)
#define N4_W2 (256 * 256 / 4)
__global__ __launch_bounds__(256)
void cvt_all_f16(const float* __restrict__ x, const float* __restrict__ W1,
                 const float* __restrict__ W2, __half* __restrict__ xh,
                 __half* __restrict__ w1h, __half* __restrict__ w2h) {
    int i = blockIdx.x * 256 + threadIdx.x;
    const float* a;
    __half* o;
    int j = i;
    if (i < N4_X)                { a = x;  o = xh;  }
    else if (i < N4_X + N4_W1)   { a = W1; o = w1h; j = i - N4_X; }
    else if (i < N4_X + N4_W1 + N4_W2) { a = W2; o = w2h; j = i - N4_X - N4_W1; }
    else return;
    float4 v = ((const float4*)a)[j];
    __half2 p0; p0.x = __float2half(v.x); p0.y = __float2half(v.y);
    __half2 p1; p1.x = __float2half(v.z); p1.y = __float2half(v.w);
    ((__half2*)o)[2 * j]     = p0;
    ((__half2*)o)[2 * j + 1] = p1;
}

// ---------------- fp16 warp-MMA GEMM: C(fp16) = A * B^T, fused al-epilogue ----------------
// CTA 128x128, BK=64; 3-stage cp.async, ONE __syncthreads per iter (early-load);
// 8 warps in 4m x 2n, warp tile 32x64: 6 ldmatrix / 16 MMA per kk per warp. (R12 champion)
#define STG_A     0
#define STG_B     16384
#define STG_BYTES 32768
#define GEMM_SMEM (3 * STG_BYTES)

template <int K>
__global__ __launch_bounds__(256, 2)
void gemm_mma(const __half* __restrict__ A, const __half* __restrict__ B,
              __half* __restrict__ C, int Mtot,
              const float* __restrict__ ws_flat, const float* __restrict__ wd_flat,
              float* __restrict__ alsP, float* __restrict__ aldP) {
    extern __shared__ __align__(1024) char smem[];
    uint32_t sb = smem_u32(smem);
    const int tid = threadIdx.x, wid = tid >> 5, lane = tid & 31;
    const int row0 = blockIdx.y * 128, col0 = blockIdx.x * 128;
    const int warp_m = wid & 3;    // 0..3 -> 32 rows each
    const int warp_n = wid >> 2;   // 0..1 -> 64 cols each
    constexpr int NIT = K / 64;

    auto load = [&](int it) {
        uint32_t st = sb + (it % 3) * STG_BYTES;
#pragma unroll
        for (int i = 0; i < 4; i++) {
            int idx = tid + i * 256;
            int r = idx >> 3, c16 = idx & 7;
            uint32_t so = swz(r * 128 + c16 * 16);
            cp16(st + STG_A + so, A + (size_t)(row0 + r) * K + it * 64 + c16 * 8);
            cp16(st + STG_B + so, B + (size_t)(col0 + r) * K + it * 64 + c16 * 8);
        }
        asm volatile("cp.async.commit_group;" ::: "memory");
    };

    float acc[2][8][4] = {};   // [mt][n8 block][frag]

    load(0);
    if (NIT > 1) load(1);

    const int lrow = lane & 15, lhi = lane >> 4;

#pragma unroll 1
    for (int it = 0; it < NIT; it++) {
        if (NIT > 1) asm volatile("cp.async.wait_group 1;" ::: "memory");
        else         asm volatile("cp.async.wait_group 0;" ::: "memory");
        __syncthreads();
        if (it + 2 < NIT) load(it + 2);        // writes oldest stage; readers retired by barrier above

        uint32_t st = sb + (it % 3) * STG_BYTES;
#pragma unroll
        for (int kk = 0; kk < 4; kk++) {
            uint32_t a[2][4];
#pragma unroll
            for (int mt = 0; mt < 2; mt++)
                ldm_x4(a[mt], st + STG_A + swz((warp_m * 32 + mt * 16 + lrow) * 128 + (kk * 2 + lhi) * 16));
#pragma unroll
            for (int bf = 0; bf < 4; bf++) {
                uint32_t b[4];
                ldm_x4(b, st + STG_B + swz((warp_n * 64 + bf * 16 + lrow) * 128 + (kk * 2 + lhi) * 16));
#pragma unroll
                for (int mt = 0; mt < 2; mt++) {
                    mma_f16(acc[mt][bf * 2 + 0], a[mt], b[0], b[2]);
                    mma_f16(acc[mt][bf * 2 + 1], a[mt], b[1], b[3]);
                }
            }
        }
    }
    __syncthreads();   // smem about to be reused as reduction buffer

    // ---- epilogue 1: store C tile as fp16 ----
#pragma unroll
    for (int mt = 0; mt < 2; mt++) {
        int row = row0 + warp_m * 32 + mt * 16 + (lane >> 2);
#pragma unroll
        for (int nb = 0; nb < 8; nb++) {
            int col = col0 + warp_n * 64 + nb * 8 + (lane & 3) * 2;
            __half2 v0; v0.x = __float2half(acc[mt][nb][0]); v0.y = __float2half(acc[mt][nb][1]);
            __half2 v1; v1.x = __float2half(acc[mt][nb][2]); v1.y = __float2half(acc[mt][nb][3]);
            *(__half2*)&C[(size_t)row * Mtot + col]       = v0;
            *(__half2*)&C[(size_t)(row + 8) * Mtot + col] = v1;
        }
    }

    // ---- epilogue 2: partial attention logits (from fp32 accumulators) ----
    const int C_head = Mtot / NHEAD;
    const int head = col0 / C_head;
    const int slot = (col0 % C_head) >> 7;
    float* bufss = (float*)smem;             // [2 warp_n][128 rows]
    float* bufsd = bufss + 256;

#pragma unroll
    for (int mt = 0; mt < 2; mt++) {
        float ss0 = 0.f, ss1 = 0.f, sd0 = 0.f, sd1 = 0.f;
#pragma unroll
        for (int nb = 0; nb < 8; nb++) {
            int c = col0 + warp_n * 64 + nb * 8 + (lane & 3) * 2;
            float w0s = ws_flat[c], w1s = ws_flat[c + 1];
            float w0d = wd_flat[c], w1d = wd_flat[c + 1];
            ss0 = fmaf(acc[mt][nb][0], w0s, fmaf(acc[mt][nb][1], w1s, ss0));
            ss1 = fmaf(acc[mt][nb][2], w0s, fmaf(acc[mt][nb][3], w1s, ss1));
            sd0 = fmaf(acc[mt][nb][0], w0d, fmaf(acc[mt][nb][1], w1d, sd0));
            sd1 = fmaf(acc[mt][nb][2], w0d, fmaf(acc[mt][nb][3], w1d, sd1));
        }
#pragma unroll
        for (int off = 1; off <= 2; off <<= 1) {
            ss0 += __shfl_xor_sync(0xffffffffu, ss0, off);
            ss1 += __shfl_xor_sync(0xffffffffu, ss1, off);
            sd0 += __shfl_xor_sync(0xffffffffu, sd0, off);
            sd1 += __shfl_xor_sync(0xffffffffu, sd1, off);
        }
        if ((lane & 3) == 0) {
            int r0 = warp_m * 32 + mt * 16 + (lane >> 2);
            bufss[warp_n * 128 + r0]     = ss0;
            bufss[warp_n * 128 + r0 + 8] = ss1;
            bufsd[warp_n * 128 + r0]     = sd0;
            bufsd[warp_n * 128 + r0 + 8] = sd1;
        }
    }
    __syncthreads();
    if (tid < 128) {
        float ss = bufss[tid] + bufss[128 + tid];
        float sd = bufsd[tid] + bufsd[128 + tid];
        size_t node = (size_t)(row0 + tid);
        alsP[(size_t)slot * PART_STRIDE + node * NHEAD + head] = ss;
        aldP[(size_t)slot * PART_STRIDE + node * NHEAD + head] = sd;
    }
}

// ---------------- layer-1 GAT combine, vectorized: 4 nodes per block, fp16 in/out ----------------
__global__ __launch_bounds__(256)
void gat_combine_l1(const __half* __restrict__ hraw, const float* __restrict__ alsP,
                    const float* __restrict__ aldP, const float* __restrict__ bias,
                    __half* __restrict__ out_hi) {
    int tid = threadIdx.x;
    int d   = blockIdx.x * 4 + (tid >> 6);
    int c4  = (tid & 63) * 4;
    bool has_prev = (d % NODES_PER) != 0;

    float4 r = *(const float4*)&bias[c4];
    float acc0 = r.x, acc1 = r.y, acc2 = r.z, acc3 = r.w;
    float o0 = 0.f, o1 = 0.f, o2 = 0.f, o3 = 0.f;
#pragma unroll
    for (int hh = 0; hh < NHEAD; hh++) {
        size_t ai = (size_t)d * NHEAD + hh;
        float als = alsP[ai] + alsP[PART_STRIDE + ai];
        float ald = aldP[ai] + aldP[PART_STRIDE + ai];
        float es  = lrelu(als + ald);
        const __half2* hsp = (const __half2*)&hraw[(size_t)d * NHEAD * HID_F + hh * HID_F + c4];
        float2 hs01 = __half22float2(hsp[0]);
        float2 hs23 = __half22float2(hsp[1]);
        if (has_prev) {
            size_t pi = (size_t)(d - 1) * NHEAD + hh;
            float alsp = alsP[pi] + alsP[PART_STRIDE + pi];
            float ep = lrelu(alsp + ald);
            float m  = fmaxf(es, ep);
            float xs = __expf(es - m), xp = __expf(ep - m);
            float inv = 0.5f / (xs + xp);
            xs *= inv; xp *= inv;
            const __half2* hpp = (const __half2*)&hraw[(size_t)(d - 1) * NHEAD * HID_F + hh * HID_F + c4];
            float2 hp01 = __half22float2(hpp[0]);
            float2 hp23 = __half22float2(hpp[1]);
            o0 += xs * hs01.x + xp * hp01.x;
            o1 += xs * hs01.y + xp * hp01.y;
            o2 += xs * hs23.x + xp * hp23.x;
            o3 += xs * hs23.y + xp * hp23.y;
        } else {
            o0 += 0.5f * hs01.x; o1 += 0.5f * hs01.y;
            o2 += 0.5f * hs23.x; o3 += 0.5f * hs23.y;
        }
    }
    acc0 = fmaxf(acc0 + o0, 0.f);
    acc1 = fmaxf(acc1 + o1, 0.f);
    acc2 = fmaxf(acc2 + o2, 0.f);
    acc3 = fmaxf(acc3 + o3, 0.f);

    __half2 ph0; ph0.x = __float2half(acc0); ph0.y = __float2half(acc1);
    __half2 ph1; ph1.x = __float2half(acc2); ph1.y = __float2half(acc3);
    size_t gid2 = ((size_t)d * HID_F + c4) >> 1;
    ((__half2*)out_hi)[gid2]     = ph0;
    ((__half2*)out_hi)[gid2 + 1] = ph1;
}

// ---------------- layer-2 combine + node heads, warp per node (fp16 h2raw) ----------------
__global__ __launch_bounds__(256)
void gat_l2_fused(const __half* __restrict__ h2raw, const float* __restrict__ alsP,
                  const float* __restrict__ aldP, const float* __restrict__ b2,
                  const float* __restrict__ Wn, const float* __restrict__ bn,
                  const float* __restrict__ Wt, const float* __restrict__ bt,
                  float* __restrict__ emb, float* __restrict__ node_pred,
                  float* __restrict__ logit) {
    int d    = (blockIdx.x * blockDim.x + threadIdx.x) >> 5;
    int lane = threadIdx.x & 31;
    if (d >= N_NODES) return;
    bool has_prev = (d % NODES_PER) != 0;

    float e[4] = {0.f, 0.f, 0.f, 0.f};
#pragma unroll
    for (int hh = 0; hh < NHEAD; hh++) {
        size_t ai = (size_t)d * NHEAD + hh;
        float als = alsP[ai];
        float ald = aldP[ai];
        float es  = lrelu(als + ald);
        const __half2* hsp = (const __half2*)&h2raw[(size_t)d * NHEAD * OUT_F + hh * OUT_F + lane * 4];
        float2 hs01 = __half22float2(hsp[0]);
        float2 hs23 = __half22float2(hsp[1]);
        if (has_prev) {
            float alsp = alsP[(size_t)(d - 1) * NHEAD + hh];
            float ep = lrelu(alsp + ald);
            float m  = fmaxf(es, ep);
            float xs = __expf(es - m), xp = __expf(ep - m);
            float inv = 1.f / (xs + xp);
            const __half2* hpp = (const __half2*)&h2raw[(size_t)(d - 1) * NHEAD * OUT_F + hh * OUT_F + lane * 4];
            float2 hp01 = __half22float2(hpp[0]);
            float2 hp23 = __half22float2(hpp[1]);
            e[0] += (xs * hs01.x + xp * hp01.x) * inv;
            e[1] += (xs * hs01.y + xp * hp01.y) * inv;
            e[2] += (xs * hs23.x + xp * hp23.x) * inv;
            e[3] += (xs * hs23.y + xp * hp23.y) * inv;
        } else {
            e[0] += hs01.x; e[1] += hs01.y; e[2] += hs23.x; e[3] += hs23.y;
        }
    }
    float4 bb = *(const float4*)&b2[lane * 4];
    e[0] = e[0] * 0.5f + bb.x;
    e[1] = e[1] * 0.5f + bb.y;
    e[2] = e[2] * 0.5f + bb.z;
    e[3] = e[3] * 0.5f + bb.w;
    float4 ev; ev.x = e[0]; ev.y = e[1]; ev.z = e[2]; ev.w = e[3];
    *(float4*)&emb[(size_t)d * OUT_F + lane * 4] = ev;

    float vals[8];
#pragma unroll
    for (int o = 0; o < 8; o++) {
        const float* w = (o < NCLS) ? &Wn[o * OUT_F] : Wt;
        float4 w4 = *(const float4*)&w[lane * 4];
        float s = e[0] * w4.x + e[1] * w4.y + e[2] * w4.z + e[3] * w4.w;
#pragma unroll
        for (int sh = 16; sh; sh >>= 1) s += __shfl_xor_sync(0xffffffffu, s, sh);
        vals[o] = s;
    }
    if (lane == 0) {
        float z[NCLS], m = -1e30f;
#pragma unroll
        for (int i = 0; i < NCLS; i++) { z[i] = vals[i] + bn[i]; m = fmaxf(m, z[i]); }
        float ssum = 0.f;
#pragma unroll
        for (int i = 0; i < NCLS; i++) { z[i] = __expf(z[i] - m); ssum += z[i]; }
        float inv = 1.f / ssum;
#pragma unroll
        for (int i = 0; i < NCLS; i++) node_pred[(size_t)d * NCLS + i] = z[i] * inv;
        logit[d] = vals[7] + bt[0];
    }
}

// ---------------- audio pooling, stage 1: per-audio softmax weights ----------------
__global__ __launch_bounds__(256)
void audio_softmax(const float* __restrict__ logit, float* __restrict__ aw) {
    __shared__ float red[256];
    int b = blockIdx.x, t = threadIdx.x;
    const float* lg = logit + b * NODES_PER;

    float m = -1e30f;
    for (int i = t; i < NODES_PER; i += 256) m = fmaxf(m, lg[i]);
    red[t] = m; __syncthreads();
    for (int s = 128; s; s >>= 1) { if (t < s) red[t] = fmaxf(red[t], red[t + s]); __syncthreads(); }
    m = red[0]; __syncthreads();

    float e0 = __expf(lg[t] - m);
    float e1 = __expf(lg[t + 256] - m);
    float e2 = __expf(lg[t + 512] - m);
    float e3 = __expf(lg[t + 768] - m);
    float e4 = __expf(lg[t + 1024] - m);
    float e5 = __expf(lg[t + 1280] - m);
    float e6 = __expf(lg[t + 1536] - m);
    float e7 = __expf(lg[t + 1792] - m);
    red[t] = ((e0 + e1) + (e2 + e3)) + ((e4 + e5) + (e6 + e7));
    __syncthreads();
    for (int s = 128; s; s >>= 1) { if (t < s) red[t] += red[t + s]; __syncthreads(); }
    float inv = 1.f / red[0];
    float* dst = aw + b * NODES_PER;
    dst[t]        = e0 * inv;
    dst[t + 256]  = e1 * inv;
    dst[t + 512]  = e2 * inv;
    dst[t + 768]  = e3 * inv;
    dst[t + 1024] = e4 * inv;
    dst[t + 1280] = e5 * inv;
    dst[t + 1536] = e6 * inv;
    dst[t + 1792] = e7 * inv;
}

// ---------------- audio pooling, stage 2: weighted sum (chunked, coalesced) ----------------
__global__ __launch_bounds__(256)
void audio_wsum(const float* __restrict__ emb, const float* __restrict__ aw,
                float* __restrict__ att) {
    __shared__ float red[8][33];
    int chunk = blockIdx.x, b = blockIdx.y;
    int w = threadIdx.x >> 5, lane = threadIdx.x & 31;
    int ch = chunk * 32 + lane;
    const float* eb = emb + (size_t)b * NODES_PER * OUT_F + ch;
    const float* wb = aw + b * NODES_PER;

    float a0 = 0.f, a1 = 0.f;
    int i0 = w * 256;
#pragma unroll 4
    for (int i = 0; i < 256; i += 2) {
        a0 = fmaf(wb[i0 + i],     eb[(size_t)(i0 + i) * OUT_F],     a0);
        a1 = fmaf(wb[i0 + i + 1], eb[(size_t)(i0 + i + 1) * OUT_F], a1);
    }
    red[w][lane] = a0 + a1;
    __syncthreads();
    if (w == 0) {
        float s = red[0][lane];
#pragma unroll
        for (int j = 1; j < 8; j++) s += red[j][lane];
        att[b * OUT_F + ch] = s;
    }
}

// ---------------- audio pooling, stage 3: Wa head ----------------
__global__ __launch_bounds__(128)
void audio_head(const float* __restrict__ att, const float* __restrict__ Wa,
                const float* __restrict__ ba, float* __restrict__ audio_pred) {
    __shared__ float red[128];
    int b = blockIdx.x, t = threadIdx.x;
    float a = att[b * OUT_F + t];
#pragma unroll
    for (int o = 0; o < 2; o++) {
        red[t] = a * Wa[o * OUT_F + t]; __syncthreads();
        for (int s = 64; s; s >>= 1) { if (t < s) red[t] += red[t + s]; __syncthreads(); }
        if (t == 0) audio_pred[b * 2 + o] = red[0] + ba[o];
        __syncthreads();
    }
}

// ---------------- launch ----------------
extern "C" void kernel_launch(void* const* d_in, const int* in_sizes, int n_in,
                              void* d_out, int out_size) {
    int wi = n_in - 14;
    const float* x   = (const float*)d_in[0];
    const float* W1  = (const float*)d_in[wi + 0];
    const float* as1 = (const float*)d_in[wi + 1];
    const float* ad1 = (const float*)d_in[wi + 2];
    const float* b1  = (const float*)d_in[wi + 3];
    const float* W2  = (const float*)d_in[wi + 4];
    const float* as2 = (const float*)d_in[wi + 5];
    const float* ad2 = (const float*)d_in[wi + 6];
    const float* b2  = (const float*)d_in[wi + 7];
    const float* Wt  = (const float*)d_in[wi + 8];
    const float* bt  = (const float*)d_in[wi + 9];
    const float* Wa  = (const float*)d_in[wi + 10];
    const float* ba  = (const float*)d_in[wi + 11];
    const float* Wn  = (const float*)d_in[wi + 12];
    const float* bn  = (const float*)d_in[wi + 13];

    float *emb, *als1p, *ald1p, *als2p, *ald2p, *logit, *aw, *att;
    __half *h1raw, *h2raw, *xh, *h1h, *w1h, *w2h;
    cudaGetSymbolAddress((void**)&h1raw, g_h1raw);
    cudaGetSymbolAddress((void**)&h2raw, g_h2raw);
    cudaGetSymbolAddress((void**)&emb,   g_emb);
    cudaGetSymbolAddress((void**)&xh,    g_xh);
    cudaGetSymbolAddress((void**)&h1h,   g_h1h);
    cudaGetSymbolAddress((void**)&w1h,   g_w1h);
    cudaGetSymbolAddress((void**)&w2h,   g_w2h);
    cudaGetSymbolAddress((void**)&als1p, g_als1p);
    cudaGetSymbolAddress((void**)&ald1p, g_ald1p);
    cudaGetSymbolAddress((void**)&als2p, g_als2p);
    cudaGetSymbolAddress((void**)&ald2p, g_ald2p);
    cudaGetSymbolAddress((void**)&logit, g_logit);
    cudaGetSymbolAddress((void**)&aw,    g_aw);
    cudaGetSymbolAddress((void**)&att,   g_att);

    float* node_pred  = (float*)d_out;
    float* audio_pred = node_pred + (size_t)N_NODES * NCLS;

    cudaFuncSetAttribute(gemm_mma<512>, cudaFuncAttributeMaxDynamicSharedMemorySize, GEMM_SMEM);
    cudaFuncSetAttribute(gemm_mma<256>, cudaFuncAttributeMaxDynamicSharedMemorySize, GEMM_SMEM);

    // conversions (x, W1, W2) in one merged launch
    {
        int n4 = N4_X + N4_W1 + N4_W2;
        cvt_all_f16<<<(n4 + 255) / 256, 256>>>(x, W1, W2, xh, w1h, w2h);
    }

    // layer 1: h1raw(fp16) = x @ W1^T [N,512] + fused al1 partials
    gemm_mma<512><<<dim3(4, N_NODES / 128), 256, GEMM_SMEM>>>(
        xh, w1h, h1raw, 512, as1, ad1, als1p, ald1p);
    gat_combine_l1<<<N_NODES / 4, 256>>>(h1raw, als1p, ald1p, b1, h1h);

    // layer 2: h2raw(fp16) = h1 @ W2^T [N,256] + fused al2 partials
    gemm_mma<256><<<dim3(2, N_NODES / 128), 256, GEMM_SMEM>>>(
        h1h, w2h, h2raw, 256, as2, ad2, als2p, ald2p);
    gat_l2_fused<<<N_NODES / 8, 256>>>(h2raw, als2p, ald2p, b2, Wn, bn, Wt, bt,
                                       emb, node_pred, logit);

    // audio head (3-stage, parallel)
    audio_softmax<<<B_AUD, 256>>>(logit, aw);
    audio_wsum<<<dim3(4, B_AUD), 256>>>(emb, aw, att);
    audio_head<<<B_AUD, 128>>>(att, Wa, ba, audio_pred);
}